// round 7
// baseline (speedup 1.0000x reference)
#include <cuda_runtime.h>
#include <cuda_bf16.h>

// Problem shapes (fixed by dataset)
#define KK 2048   // batch/k dim
#define MM 512    // feature dim m
#define NN 64     // target dim n
#define EPSV 1e-8f
#define LMAX 32

// ---------------- scratch (static device globals; no allocation) ----------------
__device__ float g_S[KK * MM];     // logits x @ w_att
__device__ float g_soft[KK * MM];  // fallback scores_soft sink
__device__ float g_hard[MM * NN];  // fallback scores_hard sink

// ---------------- Kernel 1: fp32 tiled GEMM  S = x @ w_att  (R1-proven) -----
// Chunked over k rows via k_base.
#define BM 64
#define BN 64
#define BK 16
__global__ __launch_bounds__(256) void gemm_kernel(const float* __restrict__ A,
                                                   const float* __restrict__ B,
                                                   int k_base) {
    __shared__ float As[BK][BM + 4];
    __shared__ float Bs[BK][BN];

    const int t  = threadIdx.x;
    const int tx = t & 15;
    const int ty = t >> 4;
    const int bm = k_base + blockIdx.y * BM;
    const int bn = blockIdx.x * BN;

    const int arow = t >> 2;
    const int ac4  = (t & 3) << 2;
    const int brow = t >> 4;
    const int bc4  = (t & 15) << 2;

    float acc[4][4];
#pragma unroll
    for (int i = 0; i < 4; i++)
#pragma unroll
        for (int j = 0; j < 4; j++) acc[i][j] = 0.f;

    for (int kt = 0; kt < MM; kt += BK) {
        float4 av = *(const float4*)&A[(size_t)(bm + arow) * MM + kt + ac4];
        As[ac4 + 0][arow] = av.x;
        As[ac4 + 1][arow] = av.y;
        As[ac4 + 2][arow] = av.z;
        As[ac4 + 3][arow] = av.w;
        *(float4*)&Bs[brow][bc4] =
            *(const float4*)&B[(size_t)(kt + brow) * MM + bn + bc4];
        __syncthreads();

#pragma unroll
        for (int kk = 0; kk < BK; kk++) {
            float4 a = *(const float4*)&As[kk][ty << 2];
            float4 b = *(const float4*)&Bs[kk][tx << 2];
            acc[0][0] += a.x * b.x; acc[0][1] += a.x * b.y; acc[0][2] += a.x * b.z; acc[0][3] += a.x * b.w;
            acc[1][0] += a.y * b.x; acc[1][1] += a.y * b.y; acc[1][2] += a.y * b.z; acc[1][3] += a.y * b.w;
            acc[2][0] += a.z * b.x; acc[2][1] += a.z * b.y; acc[2][2] += a.z * b.z; acc[2][3] += a.z * b.w;
            acc[3][0] += a.w * b.x; acc[3][1] += a.w * b.y; acc[3][2] += a.w * b.z; acc[3][3] += a.w * b.w;
        }
        __syncthreads();
    }

#pragma unroll
    for (int i = 0; i < 4; i++) {
        float4 v = make_float4(acc[i][0], acc[i][1], acc[i][2], acc[i][3]);
        *(float4*)&g_S[(size_t)(bm + (ty << 2) + i) * MM + bn + (tx << 2)] = v;
    }
}

// ---------------- Kernel 2: per-column top-l + hard scores  (R3-proven) -----
__global__ __launch_bounds__(32) void hard_kernel(const float* __restrict__ wb,
                                                  const int* __restrict__ lptr,
                                                  float* __restrict__ dst) {
    const int n    = blockIdx.x;
    const int lane = threadIdx.x;
    int l = lptr ? *lptr : 8;
    if (l < 1) l = 1;
    if (l > LMAX) l = LMAX;

    float v[16];
#pragma unroll
    for (int i = 0; i < 16; i++)
        v[i] = wb[(lane * 16 + i) * NN + n];

    float top[LMAX];
    for (int i = 0; i < l; i++) top[i] = -3.4e38f;
#pragma unroll
    for (int i = 0; i < 16; i++) {
        float x = v[i];
        if (x > top[l - 1]) {
            int j = l - 1;
            while (j > 0 && top[j - 1] < x) { top[j] = top[j - 1]; j--; }
            top[j] = x;
        }
    }

    int ptr = 0;
    float thr = -3.4e38f;
    for (int r = 0; r < l; r++) {
        float cand = (ptr < l) ? top[ptr] : -3.4e38f;
        float m = cand;
#pragma unroll
        for (int off = 16; off > 0; off >>= 1)
            m = fmaxf(m, __shfl_xor_sync(0xffffffffu, m, off));
        unsigned b = __ballot_sync(0xffffffffu, cand == m);
        int src = __ffs(b) - 1;
        if (lane == src) ptr++;
        thr = m;
    }

#pragma unroll
    for (int i = 0; i < 16; i++) {
        float sh = v[i] - thr + EPSV;
        sh = fminf(fmaxf(sh, -1.f), 1.f);
        float h = (sh + 1.f) * 0.5f;
        dst[(lane * 16 + i) * NN + n] = h;
    }
}

// ---------------- Kernel 3: fused softmax + epilogue ------------------------
// One block = one k-row. Block-reduce softmax of the row's 512 logits (from
// g_S) into smem, emit scores_soft once, then stream the row's 512 KB of
// out/mask_weight stores with the R2/R5-proven geometry (16 thr per m, one
// float4 each, plain .wb stores).
__global__ __launch_bounds__(256) void epi_kernel(const float* __restrict__ x,
                                                  const float* __restrict__ hard,
                                                  float* __restrict__ out_soft,
                                                  float* __restrict__ out,
                                                  float* __restrict__ mw,
                                                  int k_base) {
    const int k = k_base + blockIdx.x;
    const int t = threadIdx.x;
    const int lane = t & 31;
    const int wid  = t >> 5;

    __shared__ float soft_s[MM];
    __shared__ float xs[MM];
    __shared__ float red[8];

    const float* Srow = g_S + (size_t)k * MM;
    const float* Xrow = x   + (size_t)k * MM;

    float v0 = Srow[t];
    float v1 = Srow[t + 256];
    xs[t]       = Xrow[t];
    xs[t + 256] = Xrow[t + 256];

    // block max
    float mx = fmaxf(v0, v1);
#pragma unroll
    for (int off = 16; off > 0; off >>= 1)
        mx = fmaxf(mx, __shfl_xor_sync(0xffffffffu, mx, off));
    if (lane == 0) red[wid] = mx;
    __syncthreads();
    mx = red[0];
#pragma unroll
    for (int i = 1; i < 8; i++) mx = fmaxf(mx, red[i]);
    __syncthreads();

    // block sum of exp
    float e0 = __expf(v0 - mx);
    float e1 = __expf(v1 - mx);
    float sum = e0 + e1;
#pragma unroll
    for (int off = 16; off > 0; off >>= 1)
        sum += __shfl_xor_sync(0xffffffffu, sum, off);
    if (lane == 0) red[wid] = sum;
    __syncthreads();
    sum = red[0];
#pragma unroll
    for (int i = 1; i < 8; i++) sum += red[i];
    float inv = 1.f / sum;

    float s0 = e0 * inv + EPSV;
    float s1 = e1 * inv + EPSV;
    soft_s[t]       = s0;
    soft_s[t + 256] = s1;
    out_soft[(size_t)k * MM + t]       = s0;
    out_soft[(size_t)k * MM + t + 256] = s1;
    __syncthreads();

    // stream stores: 512 m x 16 n4-chunks = 8192 float4-pairs, 32 iters/thread
    const size_t rowbase = (size_t)k * MM * NN;
#pragma unroll 4
    for (int it = 0; it < 32; it++) {
        int id = it * 256 + t;          // 0..8191
        int n4 = (id & 15) << 2;        // 0,4,..,60
        int m  = id >> 4;               // 0..511

        float ss = soft_s[m];           // LDS broadcast (16 lanes same m)
        float xv = xs[m];
        float4 h = __ldg((const float4*)(hard + m * NN + n4));

        float4 mw4 = make_float4(h.x * ss, h.y * ss, h.z * ss, h.w * ss);
        float4 o4  = make_float4(mw4.x * xv, mw4.y * xv, mw4.z * xv, mw4.w * xv);

        size_t base = rowbase + (size_t)m * NN + n4;
        *(float4*)&out[base] = o4;
        if (mw) *(float4*)&mw[base] = mw4;
    }
}

// ---------------- launch: forked-stream pipeline ----------------------------
extern "C" void kernel_launch(void* const* d_in, const int* in_sizes, int n_in,
                              void* d_out, int out_size) {
    const float* x     = (const float*)d_in[0];
    const float* w_att = (const float*)d_in[1];
    const float* w_b   = (const float*)d_in[2];
    const int*   lptr  = (n_in > 3) ? (const int*)d_in[3] : nullptr;

    const long SZ_OUT  = (long)KK * MM * NN;
    const long SZ_HARD = (long)MM * NN;
    const long SZ_SOFT = (long)KK * MM;

    float* out_ptr = (float*)d_out;
    float* hard_dst;
    float* soft_dst;
    float* mw_ptr = nullptr;
    if ((long)out_size >= SZ_OUT + SZ_HARD + SZ_SOFT + SZ_OUT) {
        hard_dst = out_ptr + SZ_OUT;
        soft_dst = hard_dst + SZ_HARD;
        mw_ptr   = soft_dst + SZ_SOFT;
    } else {
        float* dummy;
        cudaGetSymbolAddress((void**)&dummy, g_hard);
        hard_dst = dummy;
        cudaGetSymbolAddress((void**)&dummy, g_soft);
        soft_dst = dummy;
    }

    // fork a second stream into the (possibly captured) legacy stream
    cudaStream_t s2;
    cudaStreamCreateWithFlags(&s2, cudaStreamNonBlocking);
    cudaEvent_t evRoot, evA, evB;
    cudaEventCreateWithFlags(&evRoot, cudaEventDisableTiming);
    cudaEventCreateWithFlags(&evA,    cudaEventDisableTiming);
    cudaEventCreateWithFlags(&evB,    cudaEventDisableTiming);

    cudaEventRecord(evRoot, 0);
    cudaStreamWaitEvent(s2, evRoot, 0);

    // s2: GEMM chunk A (k 0..1023), then chunk B (k 1024..2047)
    dim3 ggrid(MM / BN, (KK / 2) / BM);   // (8, 16) = 128 blocks/chunk
    gemm_kernel<<<ggrid, 256, 0, s2>>>(x, w_att, 0);
    cudaEventRecord(evA, s2);
    gemm_kernel<<<ggrid, 256, 0, s2>>>(x, w_att, KK / 2);
    cudaEventRecord(evB, s2);

    // legacy: hard scores concurrently with GEMM chunk A
    hard_kernel<<<NN, 32>>>(w_b, lptr, hard_dst);

    // legacy: epilogue chunk 0 after GEMM A, chunk 1 after GEMM B
    cudaStreamWaitEvent(0, evA, 0);
    epi_kernel<<<KK / 2, 256>>>(x, hard_dst, soft_dst, out_ptr, mw_ptr, 0);
    cudaStreamWaitEvent(0, evB, 0);
    epi_kernel<<<KK / 2, 256>>>(x, hard_dst, soft_dst, out_ptr, mw_ptr, KK / 2);
    // s2/events are intentionally not destroyed here: destroying a stream that
    // is part of an active capture is illegal; kernel_launch is only invoked a
    // handful of times (correctness + capture), so the leak is bounded.
}